// round 2
// baseline (speedup 1.0000x reference)
#include <cuda_runtime.h>
#include <math.h>

// ---------------- constants ----------------
#define NCc 128
#define NTc 256
// layer sizes
// wave conv weights: wy (5,8,16,8)=5120 floats ; wz (5,8,8,16)=5120 floats
// refine weights per step: (9,9,64,32)=165888 floats

// ---------------- scratch (static device memory; no allocations) ----------------
__device__ float g_X[524288];     // fidnet activations [H][16][W]
__device__ float g_SKIP[524288];  // skip accumulator   [H][16][W]
__device__ float g_G[262144];     // gated intermediate [H][8][W]
__device__ float g_R2[524288];    // stage-C intermediate [f(16)][m(128)][t(256)]
__device__ float g_HINP[524288];  // hinp  [c(128)][f(16)][t(256)]
__device__ float g_HFT[1048576];  // hout_ft [g(32)][c(128)][u(256)]
__device__ float g_RA[2097152];   // refine ping [ch(64)][c(128)][u(256)]
__device__ float g_RB[2097152];   // refine pong
__device__ unsigned g_FN;         // fnorm bits (non-negative float)

__device__ __forceinline__ float dfh_tanh(float x){ return tanhf(x)*0.98f + 0.02f*x; }
__device__ __forceinline__ float dfh_sig (float x){ return 0.98f/(1.0f+expf(-x)) + 0.02f*x; }

// ---------------- input dense (4->16) + build input plane ----------------
__global__ void k_dense1(const float* __restrict__ inc, const float* __restrict__ icc,
                         const float* __restrict__ times, const float* __restrict__ tin,
                         const float* __restrict__ cw, const float* __restrict__ cb)
{
    int t = blockIdx.x, c = threadIdx.x;  // t in [0,256), c in [0,128)
    float i0 = inc[c*NTc + t];
    float i1 = icc[c*NTc + t];
    float i2 = times[t];        // times[0,0,t]
    float i3 = tin[c];
    #pragma unroll
    for (int o = 0; o < 16; ++o) {
        float v = i0*cw[o] + i1*cw[16+o] + i2*cw[32+o] + i3*cw[48+o] + cb[o];
        g_X[(t*16+o)*NCc + c] = dfh_tanh(v);
    }
}

__global__ void k_zeroskip()
{
    int stride = gridDim.x*blockDim.x;
    for (int i = blockIdx.x*blockDim.x + threadIdx.x; i < 524288; i += stride)
        g_SKIP[i] = 0.0f;
}

// ---------------- wave layer: gated dilated conv pair (16ch -> 8ch) ----------------
__global__ __launch_bounds__(256,1) void k_conv12(
    const float* __restrict__ w1g, const float* __restrict__ b1,
    const float* __restrict__ w2g, const float* __restrict__ b2,
    int H, int W, int dil)
{
    __shared__ float sW1[5120];
    __shared__ float sW2[5120];
    for (int i = threadIdx.x; i < 1280; i += 256) {
        ((float4*)sW1)[i] = ((const float4*)w1g)[i];
        ((float4*)sW2)[i] = ((const float4*)w2g)[i];
    }
    __syncthreads();
    int lane = threadIdx.x & 31, warp = threadIdx.x >> 5;
    int chunks = W >> 5;                  // 4 (W=128) or 8 (W=256)
    int r = warp / chunks, q = warp - r*chunks;
    int w = (q << 5) + lane;
    int h = blockIdx.x * (8 / chunks) + r;

    float a1[8] = {0,0,0,0,0,0,0,0};
    float a2[8] = {0,0,0,0,0,0,0,0};

    for (int kh = 0; kh < 5; ++kh) {
        int hh = h + kh - 2;
        if ((unsigned)hh >= (unsigned)H) continue;
        const float* xrow = g_X + hh*16*W;
        for (int kw = 0; kw < 8; ++kw) {
            int cb0 = (q << 5) + kw*dil;
            if (cb0 >= W) break;          // uniform within warp
            int col = cb0 + lane;
            if (col < W) {
                const float* xp = xrow + col;
                const float4* wp1 = (const float4*)(sW1 + (kh*8+kw)*128);
                const float4* wp2 = (const float4*)(sW2 + (kh*8+kw)*128);
                #pragma unroll
                for (int ci = 0; ci < 16; ++ci) {
                    float xv = __ldg(xp + ci*W);
                    float4 wa = wp1[2*ci], wb = wp1[2*ci+1];
                    a1[0] += xv*wa.x; a1[1] += xv*wa.y; a1[2] += xv*wa.z; a1[3] += xv*wa.w;
                    a1[4] += xv*wb.x; a1[5] += xv*wb.y; a1[6] += xv*wb.z; a1[7] += xv*wb.w;
                    float4 wc = wp2[2*ci], wd = wp2[2*ci+1];
                    a2[0] += xv*wc.x; a2[1] += xv*wc.y; a2[2] += xv*wc.z; a2[3] += xv*wc.w;
                    a2[4] += xv*wd.x; a2[5] += xv*wd.y; a2[6] += xv*wd.z; a2[7] += xv*wd.w;
                }
            }
        }
    }
    #pragma unroll
    for (int o = 0; o < 8; ++o) {
        float v1 = a1[o] + __ldg(b1+o);
        float v2 = a2[o] + __ldg(b2+o);
        g_G[(h*8+o)*W + w] = dfh_tanh(v1) * dfh_sig(v2);
    }
}

// ---------------- wave layer: z conv (8ch -> 16ch), updates X and SKIP ----------------
__global__ __launch_bounds__(256,1) void k_convz(
    const float* __restrict__ wzg, const float* __restrict__ bz, int H, int W)
{
    __shared__ float sW[5120];
    for (int i = threadIdx.x; i < 1280; i += 256)
        ((float4*)sW)[i] = ((const float4*)wzg)[i];
    __syncthreads();
    int lane = threadIdx.x & 31, warp = threadIdx.x >> 5;
    int chunks = W >> 5;
    int r = warp / chunks, q = warp - r*chunks;
    int w = (q << 5) + lane;
    int h = blockIdx.x * (8 / chunks) + r;

    float a[16] = {0,0,0,0,0,0,0,0,0,0,0,0,0,0,0,0};

    for (int kh = 0; kh < 5; ++kh) {
        int hh = h + kh - 2;
        if ((unsigned)hh >= (unsigned)H) continue;
        const float* grow = g_G + hh*8*W;
        #pragma unroll
        for (int kw = 0; kw < 8; ++kw) {
            int col = w + kw;
            if (col < W) {
                const float* xp = grow + col;
                const float4* wp = (const float4*)(sW + (kh*8+kw)*128);
                #pragma unroll
                for (int ci = 0; ci < 8; ++ci) {
                    float xv = __ldg(xp + ci*W);
                    float4 w0 = wp[4*ci], w1 = wp[4*ci+1], w2 = wp[4*ci+2], w3 = wp[4*ci+3];
                    a[0]+=xv*w0.x;  a[1]+=xv*w0.y;  a[2]+=xv*w0.z;  a[3]+=xv*w0.w;
                    a[4]+=xv*w1.x;  a[5]+=xv*w1.y;  a[6]+=xv*w1.z;  a[7]+=xv*w1.w;
                    a[8]+=xv*w2.x;  a[9]+=xv*w2.y;  a[10]+=xv*w2.z; a[11]+=xv*w2.w;
                    a[12]+=xv*w3.x; a[13]+=xv*w3.y; a[14]+=xv*w3.z; a[15]+=xv*w3.w;
                }
            }
        }
    }
    #pragma unroll
    for (int o = 0; o < 16; ++o) {
        float z = a[o] + __ldg(bz+o);
        int idx = (h*16+o)*W + w;
        g_SKIP[idx] += z;
        g_X[idx]   += z;
    }
}

// ---------------- stage C1: 128-pt DFT over channel axis (with fftshift folded) ----------------
// R2[f,m,t] = Re( fftshift(FFT_128(mult*(c_even + i c_odd))) )  where cout = dfh_tanh(SKIP)
__global__ void k_c1()
{
    int t = blockIdx.x, f = blockIdx.y;     // 256 x 16
    __shared__ float vr[64], vi[64], tc[128], ts[128];
    int tid = threadIdx.x;                  // 128
    if (tid < 64) {
        int k = tid;
        float cr = g_SKIP[(t*16+f)*NCc + 2*k];
        float ci = g_SKIP[(t*16+f)*NCc + 2*k+1];
        cr = dfh_tanh(cr); ci = dfh_tanh(ci);
        float s = ((k==0)?0.5f:1.0f) * ((k&1)?-1.0f:1.0f);   // mult * (-1)^k (fftshift)
        vr[k] = s*cr; vi[k] = s*ci;
    }
    {
        float sv, cv; sincospif((float)tid * (1.0f/64.0f), &sv, &cv);   // theta = 2*pi*j/128
        tc[tid] = cv; ts[tid] = sv;
    }
    __syncthreads();
    int m = tid;
    float acc = 0.0f;
    #pragma unroll 8
    for (int k = 0; k < 64; ++k) {
        int j = (k*m) & 127;
        acc += vr[k]*tc[j] + vi[k]*ts[j];
    }
    g_R2[(f*128+m)*NTc + t] = acc;
}

// ---------------- stage C2: 256-pt real DFT over time; Hilbert chain collapsed ----------------
// hinp[m,2k]   = zm[k]*(-1)^k/128 * sum_t R2*cos(2pi t k/256)
// hinp[m,2k+1] = zm[k]*(-1)^k/128 * sum_t R2*sin(2pi t k/256)
__global__ void k_c2(const float* __restrict__ times)
{
    int m = blockIdx.x, f = blockIdx.y;     // 128 x 16
    __shared__ float v[256], tc[256], ts[256];
    int tid = threadIdx.x;                  // 128
    v[tid]       = g_R2[(f*128+m)*NTc + tid];
    v[tid+128]   = g_R2[(f*128+m)*NTc + tid + 128];
    {
        float sv, cv;
        sincospif((float)tid * (1.0f/128.0f), &sv, &cv);        tc[tid] = cv;      ts[tid] = sv;
        sincospif((float)(tid+128) * (1.0f/128.0f), &sv, &cv);  tc[tid+128] = cv;  ts[tid+128] = sv;
    }
    __syncthreads();
    int k = tid;
    float zm = (k==0) ? 1.0f : ((fabsf(times[2*k]) > 0.0f) ? 1.0f : 0.0f);
    float scale = zm * ((k&1)?-1.0f:1.0f) * (1.0f/128.0f);
    float ar = 0.0f, ai = 0.0f;
    #pragma unroll 8
    for (int t = 0; t < 256; ++t) {
        int j = (t*k) & 255;
        ar += v[t]*tc[j];
        ai += v[t]*ts[j];
    }
    g_HINP[(m*16+f)*NTc + 2*k]   = scale*ar;
    g_HINP[(m*16+f)*NTc + 2*k+1] = scale*ai;
}

// ---------------- dense2 (16->16) into second fidnet input ----------------
__global__ void k_dense2(const float* __restrict__ hw, const float* __restrict__ hb)
{
    int c = blockIdx.x;       // 128
    int t = threadIdx.x;      // 256
    float in[16];
    #pragma unroll
    for (int f = 0; f < 16; ++f) in[f] = g_HINP[(c*16+f)*NTc + t];
    #pragma unroll
    for (int o = 0; o < 16; ++o) {
        float acc = hb[o];
        #pragma unroll
        for (int f = 0; f < 16; ++f) acc += in[f]*hw[f*16+o];
        g_X[(c*16+o)*NTc + t] = dfh_tanh(acc);
    }
}

// ---------------- stage D: hout_ft via 256-pt DFT over time pairs ----------------
__global__ void k_stageD()
{
    int c = blockIdx.x, g = blockIdx.y;     // 128 x 32
    __shared__ float hr[128], hi[128], tc[256], ts[256];
    int tid = threadIdx.x;                  // 256
    if (tid < 128) {
        int j = tid;
        float v0, v1;
        if (g < 16) {
            float a = g_SKIP[(c*16+g)*NTc + 2*j];   v0 = dfh_tanh(a);
            float b = g_SKIP[(c*16+g)*NTc + 2*j+1]; v1 = dfh_tanh(b);
        } else {
            v0 = g_HINP[(c*16+(g-16))*NTc + 2*j];
            v1 = g_HINP[(c*16+(g-16))*NTc + 2*j+1];
        }
        float s = ((j==0)?0.5f:1.0f) * ((j&1)?-1.0f:1.0f);   // winH * (-1)^j (fftshift)
        hr[j] = s*v0; hi[j] = s*v1;
    }
    {
        float sv, cv; sincospif((float)tid * (1.0f/128.0f), &sv, &cv);  // theta = 2*pi*j/256
        tc[tid] = cv; ts[tid] = sv;
    }
    __syncthreads();
    int u = tid;
    float acc = 0.0f;
    #pragma unroll 8
    for (int j = 0; j < 128; ++j) {
        int idx = (j*u) & 255;
        acc += hr[j]*tc[idx] + hi[j]*ts[idx];
    }
    g_HFT[(g*128+c)*NTc + u] = acc;
}

// ---------------- fnorm reduction ----------------
__global__ void k_fninit(){ g_FN = 0u; }

__global__ void k_fnred()
{
    int stride = gridDim.x*blockDim.x;
    float mx = 0.0f;
    for (int i = blockIdx.x*blockDim.x + threadIdx.x; i < 1048576; i += stride)
        mx = fmaxf(mx, fabsf(g_HFT[i]));
    #pragma unroll
    for (int o = 16; o; o >>= 1) mx = fmaxf(mx, __shfl_xor_sync(0xFFFFFFFFu, mx, o));
    __shared__ float sm[8];
    int lane = threadIdx.x & 31, warp = threadIdx.x >> 5;
    if (lane == 0) sm[warp] = mx;
    __syncthreads();
    if (warp == 0) {
        mx = (lane < 8) ? sm[lane] : 0.0f;
        #pragma unroll
        for (int o = 4; o; o >>= 1) mx = fmaxf(mx, __shfl_xor_sync(0xFFFFFFFFu, mx, o));
        if (lane == 0) atomicMax(&g_FN, __float_as_uint(mx));
    }
}

__global__ void k_refinit()
{
    float inv = 1.0f/__uint_as_float(g_FN);
    int stride = gridDim.x*blockDim.x;
    for (int i = blockIdx.x*blockDim.x + threadIdx.x; i < 2097152; i += stride) {
        int ch = i >> 15; int rest = i & 32767;
        g_RA[i] = g_HFT[((ch & 31) << 15) + rest] * inv;
    }
}

// ---------------- refine conv: SAME 9x9, 64ch -> 32ch, writes ROUT[obase..obase+32) ----------------
__global__ __launch_bounds__(256,1) void k_refconv(
    const float* __restrict__ Wg, const float* __restrict__ Bg,
    int obase, int actType, int swap)
{
    const float* RIN = swap ? g_RB : g_RA;
    float*       ROUT = swap ? g_RA : g_RB;
    int c = blockIdx.x;      // 128
    int u = threadIdx.x;     // 256
    __shared__ float sw[2048];
    float acc[32];
    #pragma unroll
    for (int o = 0; o < 32; ++o) acc[o] = 0.0f;

    for (int kh = 0; kh < 9; ++kh) {
        int cc = c + kh - 4;
        bool rok = (unsigned)cc < 128u;
        for (int kw = 0; kw < 9; ++kw) {
            __syncthreads();
            const float4* wp = (const float4*)(Wg + (kh*9+kw)*2048);
            for (int i = threadIdx.x; i < 512; i += 256) ((float4*)sw)[i] = wp[i];
            __syncthreads();
            int uu = u + kw - 4;
            if (rok && (unsigned)uu < 256u) {
                const float* xp = RIN + cc*256 + uu;
                #pragma unroll 8
                for (int ci = 0; ci < 64; ++ci) {
                    float xv = __ldg(xp + ci*32768);
                    const float4* wv = (const float4*)(sw + ci*32);
                    float4 w0=wv[0], w1=wv[1], w2=wv[2], w3=wv[3];
                    float4 w4=wv[4], w5=wv[5], w6=wv[6], w7=wv[7];
                    acc[0]+=xv*w0.x;  acc[1]+=xv*w0.y;  acc[2]+=xv*w0.z;  acc[3]+=xv*w0.w;
                    acc[4]+=xv*w1.x;  acc[5]+=xv*w1.y;  acc[6]+=xv*w1.z;  acc[7]+=xv*w1.w;
                    acc[8]+=xv*w2.x;  acc[9]+=xv*w2.y;  acc[10]+=xv*w2.z; acc[11]+=xv*w2.w;
                    acc[12]+=xv*w3.x; acc[13]+=xv*w3.y; acc[14]+=xv*w3.z; acc[15]+=xv*w3.w;
                    acc[16]+=xv*w4.x; acc[17]+=xv*w4.y; acc[18]+=xv*w4.z; acc[19]+=xv*w4.w;
                    acc[20]+=xv*w5.x; acc[21]+=xv*w5.y; acc[22]+=xv*w5.z; acc[23]+=xv*w5.w;
                    acc[24]+=xv*w6.x; acc[25]+=xv*w6.y; acc[26]+=xv*w6.z; acc[27]+=xv*w6.w;
                    acc[28]+=xv*w7.x; acc[29]+=xv*w7.y; acc[30]+=xv*w7.z; acc[31]+=xv*w7.w;
                }
            }
        }
    }
    int pos = c*256 + u;
    #pragma unroll
    for (int o = 0; o < 32; ++o) {
        float v = acc[o] + __ldg(Bg+o);
        float a;
        if (actType == 0) a = dfh_tanh(v);
        else              a = (v > 0.0f ? v : 0.0f)*0.98f + 0.02f*v;
        ROUT[(obase+o)*32768 + pos] = a + RIN[(obase+o)*32768 + pos];
    }
}

// ---------------- final dense (96 -> 2) + output scaling ----------------
__global__ void k_final(const float* __restrict__ dw, const float* __restrict__ db,
                        float* __restrict__ out)
{
    int c = blockIdx.x;     // 128
    int u = threadIdx.x;    // 256
    int pos = c*256 + u;
    float fn = __uint_as_float(g_FN);
    float a0 = __ldg(db), a1 = __ldg(db+1);
    #pragma unroll 8
    for (int p = 0; p < 64; ++p) {
        float v = g_RA[p*32768 + pos] * fn;     // ref * fnorm
        a0 += v*__ldg(dw + 2*p);
        a1 += v*__ldg(dw + 2*p + 1);
    }
    #pragma unroll 8
    for (int q = 0; q < 32; ++q) {
        float v = g_HFT[q*32768 + pos];
        a0 += v*__ldg(dw + 2*(64+q));
        a1 += v*__ldg(dw + 2*(64+q) + 1);
    }
    out[pos*2]     = a0;
    out[pos*2 + 1] = a1/fn;
}

// ---------------- launch ----------------
extern "C" void kernel_launch(void* const* d_in, const int* in_sizes, int n_in,
                              void* d_out, int out_size)
{
    const float* times    = (const float*)d_in[0];
    const float* times_in = (const float*)d_in[1];
    const float* inp_nc   = (const float*)d_in[2];
    const float* inp_c    = (const float*)d_in[3];
    const float* cdw  = (const float*)d_in[4];
    const float* cdb  = (const float*)d_in[5];
    const float* cwy1 = (const float*)d_in[6];
    const float* cby1 = (const float*)d_in[7];
    const float* cwy2 = (const float*)d_in[8];
    const float* cby2 = (const float*)d_in[9];
    const float* cwz0 = (const float*)d_in[10];
    const float* cbz0 = (const float*)d_in[11];
    const float* hdw  = (const float*)d_in[12];
    const float* hdb  = (const float*)d_in[13];
    const float* hwy1 = (const float*)d_in[14];
    const float* hby1 = (const float*)d_in[15];
    const float* hwy2 = (const float*)d_in[16];
    const float* hby2 = (const float*)d_in[17];
    const float* hwz0 = (const float*)d_in[18];
    const float* hbz0 = (const float*)d_in[19];
    const float* rwr  = (const float*)d_in[20];
    const float* rbr  = (const float*)d_in[21];
    const float* rwt  = (const float*)d_in[22];
    const float* rbt  = (const float*)d_in[23];
    const float* dw   = (const float*)d_in[24];
    const float* db   = (const float*)d_in[25];
    float* out = (float*)d_out;

    static const int DILS[15] = {1,2,3,4,6,8,10,12,14,16,18,20,24,28,32};

    // ---- fidnet 1: H=NT=256 rows, W=NC=128 cols ----
    k_dense1<<<256,128>>>(inp_nc, inp_c, times, times_in, cdw, cdb);
    k_zeroskip<<<512,256>>>();
    for (int i = 0; i < 45; ++i) {
        int d = DILS[i % 15];
        k_conv12<<<128,256>>>(cwy1 + i*5120, cby1 + i*8, cwy2 + i*5120, cby2 + i*8, 256, 128, d);
        k_convz <<<128,256>>>(cwz0 + i*5120, cbz0 + i*16, 256, 128);
    }

    // ---- spectral glue (FFT/Hilbert collapsed to two DFT passes) ----
    k_c1<<<dim3(256,16),128>>>();
    k_c2<<<dim3(128,16),128>>>(times);

    // ---- fidnet 2: H=NC=128 rows, W=NT=256 cols ----
    k_dense2<<<128,256>>>(hdw, hdb);
    k_zeroskip<<<512,256>>>();
    for (int i = 0; i < 45; ++i) {
        int d = DILS[i % 15];
        k_conv12<<<128,256>>>(hwy1 + i*5120, hby1 + i*8, hwy2 + i*5120, hby2 + i*8, 128, 256, d);
        k_convz <<<128,256>>>(hwz0 + i*5120, hbz0 + i*16, 128, 256);
    }

    // ---- hout_ft ----
    k_stageD<<<dim3(128,32),256>>>();

    // ---- fnorm + refine ----
    k_fninit<<<1,1>>>();
    k_fnred<<<256,256>>>();
    k_refinit<<<512,256>>>();
    for (int i = 0; i < 4; ++i) {
        // ref = concat([tt, rr], -1) + ref  (tt -> channels 0..31, rr -> 32..63)
        k_refconv<<<128,256>>>(rwt + i*165888, rbt + i*32, 0,  0, i & 1);
        k_refconv<<<128,256>>>(rwr + i*165888, rbr + i*32, 32, 1, i & 1);
    }

    // ---- final dense + output ----
    k_final<<<128,256>>>(dw, db, out);
}

// round 3
// speedup vs baseline: 1.0117x; 1.0117x over previous
#include <cuda_runtime.h>
#include <math.h>
#include <stdint.h>

// ---------------- constants ----------------
#define NCc 128
#define NTc 256

// ---------------- scratch (static device memory; no allocations) ----------------
__device__ float g_X[524288];     // fidnet activations [H][16][W]
__device__ float g_SKIP[524288];  // skip accumulator   [H][16][W]
__device__ float g_G[262144];     // gated intermediate [H][8][W]
__device__ float g_R2[524288];    // stage-C intermediate [f(16)][m(128)][t(256)]
__device__ float g_HINP[524288];  // hinp  [c(128)][f(16)][t(256)]
__device__ float g_HFT[1048576];  // hout_ft [g(32)][c(128)][u(256)]
__device__ float g_RA[2097152];   // refine ping [ch(64)][c(128)][u(256)]
__device__ float g_RB[2097152];   // refine pong
__device__ unsigned g_FN;         // fnorm bits (non-negative float)

__device__ __forceinline__ float dfh_tanh(float x){ return tanhf(x)*0.98f + 0.02f*x; }
__device__ __forceinline__ float dfh_sig (float x){ return 0.98f/(1.0f+expf(-x)) + 0.02f*x; }

// ---------------- packed f32x2 helpers (Blackwell 2xFP32 path) ----------------
__device__ __forceinline__ void fma2(uint64_t &d, uint64_t a, uint64_t b){
    asm("fma.rn.f32x2 %0, %1, %2, %0;" : "+l"(d) : "l"(a), "l"(b));
}
__device__ __forceinline__ uint64_t pack2(float x){
    uint64_t r; asm("mov.b64 %0, {%1, %1};" : "=l"(r) : "f"(x)); return r;
}
__device__ __forceinline__ float2 unpack2(uint64_t v){
    float2 f; asm("mov.b64 {%0, %1}, %2;" : "=f"(f.x), "=f"(f.y) : "l"(v)); return f;
}

// ---------------- input dense (4->16) + build input plane ----------------
__global__ void k_dense1(const float* __restrict__ inc, const float* __restrict__ icc,
                         const float* __restrict__ times, const float* __restrict__ tin,
                         const float* __restrict__ cw, const float* __restrict__ cb)
{
    int t = blockIdx.x, c = threadIdx.x;  // t in [0,256), c in [0,128)
    float i0 = inc[c*NTc + t];
    float i1 = icc[c*NTc + t];
    float i2 = times[t];
    float i3 = tin[c];
    #pragma unroll
    for (int o = 0; o < 16; ++o) {
        float v = i0*cw[o] + i1*cw[16+o] + i2*cw[32+o] + i3*cw[48+o] + cb[o];
        g_X[(t*16+o)*NCc + c] = dfh_tanh(v);
    }
}

__global__ void k_zeroskip()
{
    int stride = gridDim.x*blockDim.x;
    for (int i = blockIdx.x*blockDim.x + threadIdx.x; i < 524288; i += stride)
        g_SKIP[i] = 0.0f;
}

// ---------------- wave layer: gated dilated conv pair (16ch -> 8ch) ----------------
// grid = 256: pb = bid>>1 selects 256 spatial positions, half = bid&1 selects out-ch half
__global__ __launch_bounds__(256) void k_conv12(
    const float* __restrict__ w1g, const float* __restrict__ b1,
    const float* __restrict__ w2g, const float* __restrict__ b2,
    int H, int W, int dil)
{
    __shared__ float4 sW1[640];   // [tap(40)][ci(16)] -> 4 floats (o half)
    __shared__ float4 sW2[640];
    int half = blockIdx.x & 1;
    int pb   = blockIdx.x >> 1;
    for (int i = threadIdx.x; i < 640; i += 256) {
        int tap = i >> 4, ci = i & 15;
        sW1[i] = *(const float4*)(w1g + tap*128 + ci*8 + half*4);
        sW2[i] = *(const float4*)(w2g + tap*128 + ci*8 + half*4);
    }
    __syncthreads();
    int lane = threadIdx.x & 31, warp = threadIdx.x >> 5;
    int chunks = W >> 5;                  // 4 (W=128) or 8 (W=256)
    int r = warp / chunks, q = warp - r*chunks;
    int w = (q << 5) + lane;
    int h = pb * (8 / chunks) + r;

    uint64_t a1[2] = {0,0};
    uint64_t a2[2] = {0,0};

    for (int kh = 0; kh < 5; ++kh) {
        int hh = h + kh - 2;
        if ((unsigned)hh >= (unsigned)H) continue;
        const float* xrow = g_X + hh*16*W;
        for (int kw = 0; kw < 8; ++kw) {
            int cb0 = (q << 5) + kw*dil;
            if (cb0 >= W) break;          // uniform within warp
            int col = cb0 + lane;
            if (col < W) {
                const float* xp = xrow + col;
                int tap = kh*8 + kw;
                const ulonglong2* wp1 = (const ulonglong2*)(sW1 + tap*16);
                const ulonglong2* wp2 = (const ulonglong2*)(sW2 + tap*16);
                #pragma unroll
                for (int ci = 0; ci < 16; ++ci) {
                    uint64_t xv2 = pack2(__ldg(xp + ci*W));
                    ulonglong2 wa = wp1[ci];
                    ulonglong2 wb = wp2[ci];
                    fma2(a1[0], xv2, wa.x); fma2(a1[1], xv2, wa.y);
                    fma2(a2[0], xv2, wb.x); fma2(a2[1], xv2, wb.y);
                }
            }
        }
    }
    #pragma unroll
    for (int p = 0; p < 2; ++p) {
        float2 v1 = unpack2(a1[p]);
        float2 v2 = unpack2(a2[p]);
        int o0 = half*4 + 2*p;
        float g0 = dfh_tanh(v1.x + __ldg(b1+o0))   * dfh_sig(v2.x + __ldg(b2+o0));
        float g1 = dfh_tanh(v1.y + __ldg(b1+o0+1)) * dfh_sig(v2.y + __ldg(b2+o0+1));
        g_G[(h*8+o0)*W + w]   = g0;
        g_G[(h*8+o0+1)*W + w] = g1;
    }
}

// ---------------- wave layer: z conv (8ch -> 16ch), updates X and SKIP ----------------
// grid = 256: pb = bid>>1, half = bid&1 selects 8 of 16 outputs
__global__ __launch_bounds__(256) void k_convz(
    const float* __restrict__ wzg, const float* __restrict__ bz, int H, int W)
{
    __shared__ float4 sW[640];  // [tap(40)][ci(8)][2 float4] = 8 floats per (tap,ci)
    int half = blockIdx.x & 1;
    int pb   = blockIdx.x >> 1;
    for (int i = threadIdx.x; i < 640; i += 256) {
        int tapci = i >> 1, part = i & 1;
        int tap = tapci >> 3, ci = tapci & 7;
        sW[i] = *(const float4*)(wzg + tap*128 + ci*16 + half*8 + part*4);
    }
    __syncthreads();
    int lane = threadIdx.x & 31, warp = threadIdx.x >> 5;
    int chunks = W >> 5;
    int r = warp / chunks, q = warp - r*chunks;
    int w = (q << 5) + lane;
    int h = pb * (8 / chunks) + r;

    uint64_t a[4] = {0,0,0,0};

    for (int kh = 0; kh < 5; ++kh) {
        int hh = h + kh - 2;
        if ((unsigned)hh >= (unsigned)H) continue;
        const float* grow = g_G + hh*8*W;
        #pragma unroll
        for (int kw = 0; kw < 8; ++kw) {
            int col = w + kw;
            if (col < W) {
                const float* xp = grow + col;
                int tap = kh*8 + kw;
                const ulonglong2* wp = (const ulonglong2*)(sW + tap*16);
                #pragma unroll
                for (int ci = 0; ci < 8; ++ci) {
                    uint64_t xv2 = pack2(__ldg(xp + ci*W));
                    ulonglong2 w01 = wp[2*ci];
                    ulonglong2 w23 = wp[2*ci+1];
                    fma2(a[0], xv2, w01.x); fma2(a[1], xv2, w01.y);
                    fma2(a[2], xv2, w23.x); fma2(a[3], xv2, w23.y);
                }
            }
        }
    }
    #pragma unroll
    for (int p = 0; p < 4; ++p) {
        float2 v = unpack2(a[p]);
        int o0 = half*8 + 2*p;
        float z0 = v.x + __ldg(bz+o0);
        float z1 = v.y + __ldg(bz+o0+1);
        int idx0 = (h*16+o0)*W + w;
        int idx1 = idx0 + W;
        g_SKIP[idx0] += z0;  g_X[idx0] += z0;
        g_SKIP[idx1] += z1;  g_X[idx1] += z1;
    }
}

// ---------------- stage C1: 128-pt DFT over channel axis (fftshift folded) ----------------
__global__ void k_c1()
{
    int t = blockIdx.x, f = blockIdx.y;     // 256 x 16
    __shared__ float vr[64], vi[64], tc[128], ts[128];
    int tid = threadIdx.x;                  // 128
    if (tid < 64) {
        int k = tid;
        float cr = g_SKIP[(t*16+f)*NCc + 2*k];
        float ci = g_SKIP[(t*16+f)*NCc + 2*k+1];
        cr = dfh_tanh(cr); ci = dfh_tanh(ci);
        float s = ((k==0)?0.5f:1.0f) * ((k&1)?-1.0f:1.0f);
        vr[k] = s*cr; vi[k] = s*ci;
    }
    {
        float sv, cv; sincospif((float)tid * (1.0f/64.0f), &sv, &cv);
        tc[tid] = cv; ts[tid] = sv;
    }
    __syncthreads();
    int m = tid;
    float acc = 0.0f;
    #pragma unroll 8
    for (int k = 0; k < 64; ++k) {
        int j = (k*m) & 127;
        acc += vr[k]*tc[j] + vi[k]*ts[j];
    }
    g_R2[(f*128+m)*NTc + t] = acc;
}

// ---------------- stage C2: 256-pt real DFT over time; Hilbert chain collapsed ----------------
__global__ void k_c2(const float* __restrict__ times)
{
    int m = blockIdx.x, f = blockIdx.y;     // 128 x 16
    __shared__ float v[256], tc[256], ts[256];
    int tid = threadIdx.x;                  // 128
    v[tid]       = g_R2[(f*128+m)*NTc + tid];
    v[tid+128]   = g_R2[(f*128+m)*NTc + tid + 128];
    {
        float sv, cv;
        sincospif((float)tid * (1.0f/128.0f), &sv, &cv);        tc[tid] = cv;      ts[tid] = sv;
        sincospif((float)(tid+128) * (1.0f/128.0f), &sv, &cv);  tc[tid+128] = cv;  ts[tid+128] = sv;
    }
    __syncthreads();
    int k = tid;
    float zm = (k==0) ? 1.0f : ((fabsf(times[2*k]) > 0.0f) ? 1.0f : 0.0f);
    float scale = zm * ((k&1)?-1.0f:1.0f) * (1.0f/128.0f);
    float ar = 0.0f, ai = 0.0f;
    #pragma unroll 8
    for (int t = 0; t < 256; ++t) {
        int j = (t*k) & 255;
        ar += v[t]*tc[j];
        ai += v[t]*ts[j];
    }
    g_HINP[(m*16+f)*NTc + 2*k]   = scale*ar;
    g_HINP[(m*16+f)*NTc + 2*k+1] = scale*ai;
}

// ---------------- dense2 (16->16) into second fidnet input ----------------
__global__ void k_dense2(const float* __restrict__ hw, const float* __restrict__ hb)
{
    int c = blockIdx.x;       // 128
    int t = threadIdx.x;      // 256
    float in[16];
    #pragma unroll
    for (int f = 0; f < 16; ++f) in[f] = g_HINP[(c*16+f)*NTc + t];
    #pragma unroll
    for (int o = 0; o < 16; ++o) {
        float acc = hb[o];
        #pragma unroll
        for (int f = 0; f < 16; ++f) acc += in[f]*hw[f*16+o];
        g_X[(c*16+o)*NTc + t] = dfh_tanh(acc);
    }
}

// ---------------- stage D: hout_ft via 256-pt DFT over time pairs ----------------
__global__ void k_stageD()
{
    int c = blockIdx.x, g = blockIdx.y;     // 128 x 32
    __shared__ float hr[128], hi[128], tc[256], ts[256];
    int tid = threadIdx.x;                  // 256
    if (tid < 128) {
        int j = tid;
        float v0, v1;
        if (g < 16) {
            float a = g_SKIP[(c*16+g)*NTc + 2*j];   v0 = dfh_tanh(a);
            float b = g_SKIP[(c*16+g)*NTc + 2*j+1]; v1 = dfh_tanh(b);
        } else {
            v0 = g_HINP[(c*16+(g-16))*NTc + 2*j];
            v1 = g_HINP[(c*16+(g-16))*NTc + 2*j+1];
        }
        float s = ((j==0)?0.5f:1.0f) * ((j&1)?-1.0f:1.0f);
        hr[j] = s*v0; hi[j] = s*v1;
    }
    {
        float sv, cv; sincospif((float)tid * (1.0f/128.0f), &sv, &cv);
        tc[tid] = cv; ts[tid] = sv;
    }
    __syncthreads();
    int u = tid;
    float acc = 0.0f;
    #pragma unroll 8
    for (int j = 0; j < 128; ++j) {
        int idx = (j*u) & 255;
        acc += hr[j]*tc[idx] + hi[j]*ts[idx];
    }
    g_HFT[(g*128+c)*NTc + u] = acc;
}

// ---------------- fnorm reduction ----------------
__global__ void k_fninit(){ g_FN = 0u; }

__global__ void k_fnred()
{
    int stride = gridDim.x*blockDim.x;
    float mx = 0.0f;
    for (int i = blockIdx.x*blockDim.x + threadIdx.x; i < 1048576; i += stride)
        mx = fmaxf(mx, fabsf(g_HFT[i]));
    #pragma unroll
    for (int o = 16; o; o >>= 1) mx = fmaxf(mx, __shfl_xor_sync(0xFFFFFFFFu, mx, o));
    __shared__ float sm[8];
    int lane = threadIdx.x & 31, warp = threadIdx.x >> 5;
    if (lane == 0) sm[warp] = mx;
    __syncthreads();
    if (warp == 0) {
        mx = (lane < 8) ? sm[lane] : 0.0f;
        #pragma unroll
        for (int o = 4; o; o >>= 1) mx = fmaxf(mx, __shfl_xor_sync(0xFFFFFFFFu, mx, o));
        if (lane == 0) atomicMax(&g_FN, __float_as_uint(mx));
    }
}

__global__ void k_refinit()
{
    float inv = 1.0f/__uint_as_float(g_FN);
    int stride = gridDim.x*blockDim.x;
    for (int i = blockIdx.x*blockDim.x + threadIdx.x; i < 2097152; i += stride) {
        int ch = i >> 15; int rest = i & 32767;
        g_RA[i] = g_HFT[((ch & 31) << 15) + rest] * inv;
    }
}

// ---------------- refine conv: SAME 9x9, 64ch -> 32ch ----------------
// grid = 256: c = bid>>1, osel = bid&1 selects which 16 of the 32 conv outputs
__global__ __launch_bounds__(256) void k_refconv(
    const float* __restrict__ Wg, const float* __restrict__ Bg,
    int obase, int actType, int swap)
{
    const float* RIN  = swap ? g_RB : g_RA;
    float*       ROUT = swap ? g_RA : g_RB;
    int c    = blockIdx.x >> 1;   // 128 rows
    int osel = blockIdx.x & 1;    // which 16-output half
    int u    = threadIdx.x;       // 256
    __shared__ float4 sw[2304];   // per-kh stage: [kw(9)][ci(64)] x 16 floats = 36KB

    uint64_t acc[8] = {0,0,0,0,0,0,0,0};

    for (int kh = 0; kh < 9; ++kh) {
        __syncthreads();
        const float* wbase = Wg + (kh*9)*2048 + osel*16;
        for (int i = threadIdx.x; i < 2304; i += 256) {
            int kwci = i >> 2, part = i & 3;
            sw[i] = *(const float4*)(wbase + kwci*32 + part*4);
        }
        __syncthreads();

        int cc = c + kh - 4;
        if ((unsigned)cc >= 128u) continue;
        for (int kw = 0; kw < 9; ++kw) {
            int uu = u + kw - 4;
            if ((unsigned)uu >= 256u) continue;
            const float* xp = RIN + cc*256 + uu;
            const ulonglong2* wp = (const ulonglong2*)(sw + kw*256);
            #pragma unroll 4
            for (int ci = 0; ci < 64; ++ci) {
                uint64_t xv2 = pack2(__ldg(xp + ci*32768));
                ulonglong2 w0 = wp[4*ci];
                ulonglong2 w1 = wp[4*ci+1];
                ulonglong2 w2 = wp[4*ci+2];
                ulonglong2 w3 = wp[4*ci+3];
                fma2(acc[0], xv2, w0.x); fma2(acc[1], xv2, w0.y);
                fma2(acc[2], xv2, w1.x); fma2(acc[3], xv2, w1.y);
                fma2(acc[4], xv2, w2.x); fma2(acc[5], xv2, w2.y);
                fma2(acc[6], xv2, w3.x); fma2(acc[7], xv2, w3.y);
            }
        }
    }
    int pos = c*256 + u;
    #pragma unroll
    for (int p = 0; p < 8; ++p) {
        float2 v2 = unpack2(acc[p]);
        #pragma unroll
        for (int s = 0; s < 2; ++s) {
            int k = osel*16 + 2*p + s;          // conv-local out channel
            float v = (s ? v2.y : v2.x) + __ldg(Bg + k);
            float a;
            if (actType == 0) a = dfh_tanh(v);
            else              a = (v > 0.0f ? v : 0.0f)*0.98f + 0.02f*v;
            int ch = obase + k;
            ROUT[ch*32768 + pos] = a + RIN[ch*32768 + pos];
        }
    }
}

// ---------------- final dense (96 -> 2) + output scaling ----------------
__global__ void k_final(const float* __restrict__ dw, const float* __restrict__ db,
                        float* __restrict__ out)
{
    int c = blockIdx.x;     // 128
    int u = threadIdx.x;    // 256
    int pos = c*256 + u;
    float fn = __uint_as_float(g_FN);
    float a0 = __ldg(db), a1 = __ldg(db+1);
    #pragma unroll 8
    for (int p = 0; p < 64; ++p) {
        float v = g_RA[p*32768 + pos] * fn;
        a0 += v*__ldg(dw + 2*p);
        a1 += v*__ldg(dw + 2*p + 1);
    }
    #pragma unroll 8
    for (int q = 0; q < 32; ++q) {
        float v = g_HFT[q*32768 + pos];
        a0 += v*__ldg(dw + 2*(64+q));
        a1 += v*__ldg(dw + 2*(64+q) + 1);
    }
    out[pos*2]     = a0;
    out[pos*2 + 1] = a1/fn;
}

// ---------------- launch ----------------
extern "C" void kernel_launch(void* const* d_in, const int* in_sizes, int n_in,
                              void* d_out, int out_size)
{
    const float* times    = (const float*)d_in[0];
    const float* times_in = (const float*)d_in[1];
    const float* inp_nc   = (const float*)d_in[2];
    const float* inp_c    = (const float*)d_in[3];
    const float* cdw  = (const float*)d_in[4];
    const float* cdb  = (const float*)d_in[5];
    const float* cwy1 = (const float*)d_in[6];
    const float* cby1 = (const float*)d_in[7];
    const float* cwy2 = (const float*)d_in[8];
    const float* cby2 = (const float*)d_in[9];
    const float* cwz0 = (const float*)d_in[10];
    const float* cbz0 = (const float*)d_in[11];
    const float* hdw  = (const float*)d_in[12];
    const float* hdb  = (const float*)d_in[13];
    const float* hwy1 = (const float*)d_in[14];
    const float* hby1 = (const float*)d_in[15];
    const float* hwy2 = (const float*)d_in[16];
    const float* hby2 = (const float*)d_in[17];
    const float* hwz0 = (const float*)d_in[18];
    const float* hbz0 = (const float*)d_in[19];
    const float* rwr  = (const float*)d_in[20];
    const float* rbr  = (const float*)d_in[21];
    const float* rwt  = (const float*)d_in[22];
    const float* rbt  = (const float*)d_in[23];
    const float* dw   = (const float*)d_in[24];
    const float* db   = (const float*)d_in[25];
    float* out = (float*)d_out;

    static const int DILS[15] = {1,2,3,4,6,8,10,12,14,16,18,20,24,28,32};

    // ---- fidnet 1: H=NT=256 rows, W=NC=128 cols ----
    k_dense1<<<256,128>>>(inp_nc, inp_c, times, times_in, cdw, cdb);
    k_zeroskip<<<512,256>>>();
    for (int i = 0; i < 45; ++i) {
        int d = DILS[i % 15];
        k_conv12<<<256,256>>>(cwy1 + i*5120, cby1 + i*8, cwy2 + i*5120, cby2 + i*8, 256, 128, d);
        k_convz <<<256,256>>>(cwz0 + i*5120, cbz0 + i*16, 256, 128);
    }

    // ---- spectral glue (FFT/Hilbert collapsed to two DFT passes) ----
    k_c1<<<dim3(256,16),128>>>();
    k_c2<<<dim3(128,16),128>>>(times);

    // ---- fidnet 2: H=NC=128 rows, W=NT=256 cols ----
    k_dense2<<<128,256>>>(hdw, hdb);
    k_zeroskip<<<512,256>>>();
    for (int i = 0; i < 45; ++i) {
        int d = DILS[i % 15];
        k_conv12<<<256,256>>>(hwy1 + i*5120, hby1 + i*8, hwy2 + i*5120, hby2 + i*8, 128, 256, d);
        k_convz <<<256,256>>>(hwz0 + i*5120, hbz0 + i*16, 128, 256);
    }

    // ---- hout_ft ----
    k_stageD<<<dim3(128,32),256>>>();

    // ---- fnorm + refine ----
    k_fninit<<<1,1>>>();
    k_fnred<<<256,256>>>();
    k_refinit<<<512,256>>>();
    for (int i = 0; i < 4; ++i) {
        k_refconv<<<256,256>>>(rwt + i*165888, rbt + i*32, 0,  0, i & 1);
        k_refconv<<<256,256>>>(rwr + i*165888, rbr + i*32, 32, 1, i & 1);
    }

    // ---- final dense + output ----
    k_final<<<128,256>>>(dw, db, out);
}